// round 15
// baseline (speedup 1.0000x reference)
#include <cuda_runtime.h>

typedef unsigned long long ull;
typedef long long ll;

#define HDIM 64
#define GDIM 192  // 3*HDIM
#define MAXT 256
#define MAXB 16384
#define MAXV 102400
#define NTHR 128  // (k-half) x (64 units)
#define ROWS 4    // rows per CTA

#define S_RZ (-1.4426950408889634f)  // -log2(e): r,z gates
#define S_N (2.8853900817779268f)    // 2*log2(e): n gate

// ---------------- device globals (no allocation allowed) ----------------
__device__ int g_tok64;
__device__ int g_pos64;
__device__ int g_hist[256];
__device__ int g_order[MAXB];
__device__ float g_proj[(size_t)MAXV * GDIM];  // (emb @ W_ih^T) * gate-scale

// ---------------- helpers ----------------
__device__ __forceinline__ ull ffma2(ull a, ull b, ull c) {
  ull d;
  asm("fma.rn.f32x2 %0, %1, %2, %3;" : "=l"(d) : "l"(a), "l"(b), "l"(c));
  return d;
}
__device__ __forceinline__ float pair_sum(ull a) {
  unsigned lo, hi;
  asm("mov.b64 {%0, %1}, %2;" : "=r"(lo), "=r"(hi) : "l"(a));
  return __uint_as_float(lo) + __uint_as_float(hi);
}
__device__ __forceinline__ ull mul2s(ull a, float s) {
  unsigned lo, hi;
  asm("mov.b64 {%0, %1}, %2;" : "=r"(lo), "=r"(hi) : "l"(a));
  float x = __uint_as_float(lo) * s, y = __uint_as_float(hi) * s;
  ull d;
  asm("mov.b64 %0, {%1, %2};"
      : "=l"(d)
      : "r"(__float_as_uint(x)), "r"(__float_as_uint(y)));
  return d;
}
__device__ __forceinline__ float rcp_fast(float x) {
  float y;
  asm("rcp.approx.f32 %0, %1;" : "=f"(y) : "f"(x));
  return y;
}
__device__ __forceinline__ float ex2(float x) {
  float y;
  asm("ex2.approx.f32 %0, %1;" : "=f"(y) : "f"(x));
  return y;
}
__device__ __forceinline__ int load_len_(const void* sp, int b, int T, int p64) {
  int v = p64 ? (int)((const ll*)sp)[b] : ((const int*)sp)[b];
  return min(max(v, 1), T);
}
__device__ __forceinline__ int load_tok_(const void* st, ll idx, int t64) {
  return t64 ? (int)((const ll*)st)[idx] : ((const int*)st)[idx];
}

// ---------------- preamble 1: dtype detect + length histogram (1 CTA) -------
__global__ void k_prep(const int* tok, const int* pos, int B, int T) {
  __shared__ int h_sm[256];
  int i = threadIdx.x;
  if (i == 0) {
    int t64 = 1, p64 = 1;
#pragma unroll
    for (int k = 1; k < 32; k += 2) {
      if (tok[k] != 0) t64 = 0;
      if (pos[k] != 0) p64 = 0;
    }
    g_tok64 = t64;
    g_pos64 = p64;
  }
  h_sm[i] = 0;
  __syncthreads();
  int p64 = g_pos64;
  for (int b = i; b < B; b += 256) {
    int len = load_len_(pos, b, T, p64);
    atomicAdd(&h_sm[min(T - len, 255)], 1);  // bin 0 = longest
  }
  __syncthreads();
  g_hist[i] = h_sm[i];
}

// ---------------- preamble 2: scan + scatter (1 CTA) ----------------
__global__ void k_scanscatter(const void* pos, int B, int T) {
  __shared__ int v[256];
  __shared__ int cur[256];
  int i = threadIdx.x;
  int x = g_hist[i];
  v[i] = x;
  __syncthreads();
#pragma unroll
  for (int off = 1; off < 256; off <<= 1) {
    int t = (i >= off) ? v[i - off] : 0;
    __syncthreads();
    v[i] += t;
    __syncthreads();
  }
  cur[i] = v[i] - x;
  __syncthreads();
  int p64 = g_pos64;
  for (int b = i; b < B; b += 256) {
    int len = load_len_(pos, b, T, p64);
    int bin = min(T - len, 255);
    int p = atomicAdd(&cur[bin], 1);
    if (p < MAXB) g_order[p] = b;
  }
}

// ---------------- vocab projection: g_proj = (emb @ W_ih^T) * scale --------
// k-split recipe, RPI 8 (R13/R14 config): CTA = 128 threads, kh = (tid>>4)&1,
// j = (tid&15)|((tid>>5)<<4). Thread holds HALF W_ih rows {j,64+j,128+j}
// prescaled (48 ull regs), partial dots for 8 staged emb rows x 3 gates,
// shfl.xor(16) combines halves. cp.async triple buffer at distance 2.
#define PROJ_RPI 8
__global__ void __launch_bounds__(NTHR, 3) k_proj(const float* __restrict__ emb,
                                                  const float* __restrict__ W_ih,
                                                  int V) {
  __shared__ __align__(16) float e_sm[3][PROJ_RPI][2][36];  // [slot][row][kh][32+pad]
  const int tid = threadIdx.x;
  const int kh = (tid >> 4) & 1;
  const int j = (tid & 15) | ((tid >> 5) << 4);
  const int rbase = kh * 4;  // own output rows within staged block

  // W_ih half-rows for unit j, 3 gates, PRESCALED: 96 floats -> 48 ull regs
  ull wr[16], wz[16], wn[16];
  {
    const ulonglong2* p0 = (const ulonglong2*)(W_ih + j * HDIM + kh * 32);
    const ulonglong2* p1 = (const ulonglong2*)(W_ih + (HDIM + j) * HDIM + kh * 32);
    const ulonglong2* p2 = (const ulonglong2*)(W_ih + (2 * HDIM + j) * HDIM + kh * 32);
#pragma unroll
    for (int k = 0; k < 8; k++) {
      ulonglong2 a = p0[k];
      wr[2 * k] = mul2s(a.x, S_RZ);
      wr[2 * k + 1] = mul2s(a.y, S_RZ);
      ulonglong2 b = p1[k];
      wz[2 * k] = mul2s(b.x, S_RZ);
      wz[2 * k + 1] = mul2s(b.y, S_RZ);
      ulonglong2 c = p2[k];
      wn[2 * k] = mul2s(c.x, S_N);
      wn[2 * k + 1] = mul2s(c.y, S_N);
    }
  }

  int per = (V + gridDim.x - 1) / gridDim.x;
  per = (per + PROJ_RPI - 1) & ~(PROJ_RPI - 1);
  const int vbeg = blockIdx.x * per;
  const int vend = min(vbeg + per, V);
  if (vbeg >= vend) return;
  const int niter = (vend - vbeg + PROJ_RPI - 1) / PROJ_RPI;

  const unsigned smem_base = (unsigned)__cvta_generic_to_shared(e_sm);

  // loaders: all 128 threads, one 16B cp.async (8 rows x 16 float4).
  const int lrow = tid >> 4, lchunk = tid & 15;
  const unsigned lpad_off =
      (unsigned)(((lchunk >> 3) * 36 + (lchunk & 7) * 4) * 4);  // bytes in row

  auto issue_block = [&](int it, int s) {
    int v = vbeg + it * PROJ_RPI + lrow;
    if (v >= vend) v = vend - 1;  // clamp: data unused, address valid
    unsigned dst =
        smem_base + (unsigned)((s * PROJ_RPI + lrow) * 72 * 4) + lpad_off;
    const float* src = emb + (ll)v * HDIM + lchunk * 4;
    asm volatile("cp.async.cg.shared.global [%0], [%1], 16;" ::"r"(dst),
                 "l"(src));
    asm volatile("cp.async.commit_group;" ::: "memory");
  };

  issue_block(0, 0);
  if (niter > 1) issue_block(1, 1);

  for (int it = 0; it < niter; it++) {
    const int slot = it % 3;
    if (it + 1 < niter)
      asm volatile("cp.async.wait_group 1;" ::: "memory");
    else
      asm volatile("cp.async.wait_group 0;" ::: "memory");
    __syncthreads();

    if (it + 2 < niter)
      issue_block(it + 2, (it + 2) % 3);
    else
      asm volatile("cp.async.commit_group;" ::: "memory");

    ull acc[PROJ_RPI][3];
#pragma unroll
    for (int r = 0; r < PROJ_RPI; r++) {
      acc[r][0] = 0ull;
      acc[r][1] = 0ull;
      acc[r][2] = 0ull;
    }
#pragma unroll
    for (int k = 0; k < 8; k++) {
#pragma unroll
      for (int r = 0; r < PROJ_RPI; r++) {
        ulonglong2 q = ((const ulonglong2*)e_sm[slot][r][kh])[k];
        acc[r][0] = ffma2(wr[2 * k], q.x, acc[r][0]);
        acc[r][0] = ffma2(wr[2 * k + 1], q.y, acc[r][0]);
        acc[r][1] = ffma2(wz[2 * k], q.x, acc[r][1]);
        acc[r][1] = ffma2(wz[2 * k + 1], q.y, acc[r][1]);
        acc[r][2] = ffma2(wn[2 * k], q.x, acc[r][2]);
        acc[r][2] = ffma2(wn[2 * k + 1], q.y, acc[r][2]);
      }
    }

    float f[PROJ_RPI][3];
#pragma unroll
    for (int r = 0; r < PROJ_RPI; r++) {
#pragma unroll
      for (int gg = 0; gg < 3; gg++) {
        float p = pair_sum(acc[r][gg]);
        f[r][gg] = p + __shfl_xor_sync(0xffffffffu, p, 16);
      }
    }

    const int v0 = vbeg + it * PROJ_RPI + rbase;
#pragma unroll
    for (int r = 0; r < 4; r++) {
      int v = v0 + r;
      if (v < vend) {
        float* dst = g_proj + (ll)v * GDIM + j;
        dst[0] = f[rbase + r][0];
        dst[64] = f[rbase + r][1];
        dst[128] = f[rbase + r][2];
      }
    }
    __syncthreads();
  }
  asm volatile("cp.async.wait_group 0;" ::: "memory");
}

// ---------------- fused GRU recurrence (4 CTAs/SM: W_r/W_z in SMEM) --------
// CTA = 128 threads. kh = (tid>>4)&1, j = (tid&15)|((tid>>5)<<4).
// W_r/W_z half-rows live PRESCALED in SMEM (per-thread 272B-strided layout:
// bank-offset 4 -> optimal 4-wavefront LDS.128, immune to L1 thrash);
// W_n half-rows in registers (32 regs). Thread: partial dots for 4 rows x 3
// gates, shfl.xor(16) combines halves, ex2/rcp gates + h-update for own 2
// rows (h carried in registers). gi prefetched one step ahead. One barrier
// per step; 2x unrolled. regs ~110 -> 4 CTAs/SM, 16 warps.
#define WSTRIDE 17  // ulonglong2 per thread (16 used + 1 pad) = 272B
__global__ void __launch_bounds__(NTHR, 4) k_gru(
    const void* __restrict__ seq_token, const void* __restrict__ seq_pos,
    const float* __restrict__ W_hh, float* __restrict__ out, int B, int T) {
  __shared__ ulonglong2 w_sm[NTHR * WSTRIDE];  // 34816 B
  __shared__ int tok_sm[ROWS][MAXT];           // byte offsets: tok * GDIM * 4
  __shared__ __align__(16) float h_sm[2][ROWS][2][36];  // [buf][row][kh][32+pad]
  __shared__ int s_row[ROWS], s_len[ROWS];

  const int tid = threadIdx.x;
  const int kh = (tid >> 4) & 1;
  const int j = (tid & 15) | ((tid >> 5) << 4);
  const int rA = kh * 2, rB = rA + 1;  // own rows
  const int tok64 = g_tok64;
  const int jh = j >> 5, jl = j & 31;

  if (tid < ROWS) {
    int idx = ROWS * blockIdx.x + tid;
    int row = (idx < B) ? g_order[idx] : -1;
    s_row[tid] = row;
    s_len[tid] = (row >= 0) ? load_len_(seq_pos, row, T, g_pos64) : 0;
  }
  __syncthreads();
  int tmax = max(max(s_len[0], s_len[1]), max(s_len[2], s_len[3]));
  int tsteps = (tmax + 1) & ~1;
  if (tsteps > MAXT - 1) tsteps = MAXT - 1;
  if (tsteps < tmax) tsteps = tmax;
  const int lenA = s_len[rA], lenB = s_len[rB];

  // stage token BYTE offsets into smem (+ zero sentinel for prefetch tail)
#pragma unroll
  for (int r = 0; r < ROWS; r++) {
    int rw = s_row[r];
    for (int i = tid; i < tsteps; i += NTHR) {
      int tk = (rw >= 0 && i < T) ? load_tok_(seq_token, (ll)rw * T + i, tok64) : 0;
      tok_sm[r][i] = tk * (GDIM * 4);
    }
  }
  if (tid < ROWS) tok_sm[tid][tsteps] = 0;  // sentinel

  // W_hh half-rows: r,z gates prescaled -> SMEM; n gate prescaled -> regs
  ull wn[16];
  {
    const ulonglong2* p0 = (const ulonglong2*)(W_hh + j * HDIM + kh * 32);
    const ulonglong2* p1 = (const ulonglong2*)(W_hh + (HDIM + j) * HDIM + kh * 32);
    const ulonglong2* p2 = (const ulonglong2*)(W_hh + (2 * HDIM + j) * HDIM + kh * 32);
    ulonglong2* myw = w_sm + tid * WSTRIDE;
#pragma unroll
    for (int k = 0; k < 8; k++) {
      ulonglong2 a = p0[k];
      ulonglong2 qa;
      qa.x = mul2s(a.x, S_RZ);
      qa.y = mul2s(a.y, S_RZ);
      myw[k] = qa;
      ulonglong2 b = p1[k];
      ulonglong2 qb;
      qb.x = mul2s(b.x, S_RZ);
      qb.y = mul2s(b.y, S_RZ);
      myw[8 + k] = qb;
      ulonglong2 c = p2[k];
      wn[2 * k] = mul2s(c.x, S_N);
      wn[2 * k + 1] = mul2s(c.y, S_N);
    }
  }
  const ulonglong2* __restrict__ myw = w_sm + tid * WSTRIDE;

  // init h = 0 in buffer 0 (own-row slots); own h also lives in registers
  float hoA = 0.0f, hoB = 0.0f;
  h_sm[0][rA][jh][jl] = 0.0f;
  h_sm[0][rB][jh][jl] = 0.0f;
  __syncthreads();  // tok_sm + h + w_sm ready

  const char* gbaseJ = (const char*)g_proj + (unsigned)(j * 4);

  // gi for t=0 (own 2 rows x 3 gates)
  float grA, gzA, gnA, grB, gzB, gnB;
  {
    const float* pA = (const float*)(gbaseJ + (unsigned)tok_sm[rA][0]);
    const float* pB = (const float*)(gbaseJ + (unsigned)tok_sm[rB][0]);
    grA = pA[0]; gzA = pA[64]; gnA = pA[128];
    grB = pB[0]; gzB = pB[64]; gnB = pB[128];
  }

// one GRU step: prefetches gi for tt+1, consumes gi of tt, updates h.
#define GRU_STEP(CUR, NXT, tt)                                                 \
  do {                                                                         \
    const float* pA = (const float*)(gbaseJ + (unsigned)tok_sm[rA][(tt) + 1]); \
    const float* pB = (const float*)(gbaseJ + (unsigned)tok_sm[rB][(tt) + 1]); \
    float qrA = pA[0], qzA = pA[64], qnA = pA[128];                            \
    float qrB = pB[0], qzB = pB[64], qnB = pB[128];                            \
    ull acc[ROWS][3];                                                          \
    _Pragma("unroll") for (int r = 0; r < ROWS; r++) {                         \
      acc[r][0] = 0ull;                                                        \
      acc[r][1] = 0ull;                                                        \
      acc[r][2] = 0ull;                                                        \
    }                                                                          \
    _Pragma("unroll") for (int k = 0; k < 8; k++) {                            \
      ulonglong2 wrq = myw[k];                                                 \
      ulonglong2 wzq = myw[8 + k];                                             \
      _Pragma("unroll") for (int r = 0; r < ROWS; r++) {                       \
        ulonglong2 hq = ((const ulonglong2*)h_sm[CUR][r][kh])[k];              \
        acc[r][0] = ffma2(wrq.x, hq.x, acc[r][0]);                             \
        acc[r][0] = ffma2(wrq.y, hq.y, acc[r][0]);                             \
        acc[r][1] = ffma2(wzq.x, hq.x, acc[r][1]);                             \
        acc[r][1] = ffma2(wzq.y, hq.y, acc[r][1]);                             \
        acc[r][2] = ffma2(wn[2 * k], hq.x, acc[r][2]);                         \
        acc[r][2] = ffma2(wn[2 * k + 1], hq.y, acc[r][2]);                     \
      }                                                                        \
    }                                                                          \
    float f[ROWS][3];                                                          \
    _Pragma("unroll") for (int r = 0; r < ROWS; r++) {                         \
      _Pragma("unroll") for (int gg = 0; gg < 3; gg++) {                       \
        float p = pair_sum(acc[r][gg]);                                        \
        f[r][gg] = p + __shfl_xor_sync(0xffffffffu, p, 16);                    \
      }                                                                        \
    }                                                                          \
    {                                                                          \
      float rrA = rcp_fast(1.0f + ex2(grA + f[rA][0]));                        \
      float zzA = rcp_fast(1.0f + ex2(gzA + f[rA][1]));                        \
      float nnA = 1.0f - 2.0f * rcp_fast(ex2(gnA + rrA * f[rA][2]) + 1.0f);    \
      float hnA = (1.0f - zzA) * nnA + zzA * hoA;                              \
      hoA = ((tt) < lenA) ? hnA : hoA;                                         \
      h_sm[NXT][rA][jh][jl] = hoA;                                             \
      float rrB = rcp_fast(1.0f + ex2(grB + f[rB][0]));                        \
      float zzB = rcp_fast(1.0f + ex2(gzB + f[rB][1]));                        \
      float nnB = 1.0f - 2.0f * rcp_fast(ex2(gnB + rrB * f[rB][2]) + 1.0f);    \
      float hnB = (1.0f - zzB) * nnB + zzB * hoB;                              \
      hoB = ((tt) < lenB) ? hnB : hoB;                                         \
      h_sm[NXT][rB][jh][jl] = hoB;                                             \
    }                                                                          \
    grA = qrA; gzA = qzA; gnA = qnA;                                           \
    grB = qrB; gzB = qzB; gnB = qnB;                                           \
    __syncthreads();                                                           \
  } while (0)

  int t = 0;
  for (; t + 1 < tsteps; t += 2) {
    GRU_STEP(0, 1, t);
    GRU_STEP(1, 0, t + 1);
  }
  if (t < tsteps) {  // odd tail
    GRU_STEP(0, 1, t);
  }
#undef GRU_STEP

  {
    int row = s_row[rA];
    if (row >= 0) out[(ll)row * HDIM + j] = hoA;
    row = s_row[rB];
    if (row >= 0) out[(ll)row * HDIM + j] = hoB;
  }
}

// ---------------- launch ----------------
extern "C" void kernel_launch(void* const* d_in, const int* in_sizes, int n_in,
                              void* d_out, int out_size) {
  const void* tok = d_in[0];
  const void* pos = d_in[1];
  const float* emb = (const float*)d_in[2];
  const float* wih = (const float*)d_in[3];
  const float* whh = (const float*)d_in[4];
  float* out = (float*)d_out;

  const int B = in_sizes[1];
  const int T = in_sizes[0] / (B > 0 ? B : 1);
  int V = in_sizes[2] / HDIM;
  if (V > MAXV) V = MAXV;

  k_prep<<<1, 256>>>((const int*)tok, (const int*)pos, B, T);
  k_scanscatter<<<1, 256>>>(pos, B, T);
  k_proj<<<1184, NTHR>>>(emb, wih, V);

  const int nblk = (B + ROWS - 1) / ROWS;
  k_gru<<<nblk, NTHR>>>(tok, pos, whh, out, B, T);
}

// round 16
// speedup vs baseline: 1.1586x; 1.1586x over previous
#include <cuda_runtime.h>

typedef unsigned long long ull;
typedef long long ll;

#define HDIM 64
#define GDIM 192  // 3*HDIM
#define MAXT 256
#define MAXB 16384
#define MAXV 102400
#define NTHR 128  // (k-half) x (64 units)
#define ROWS 4    // rows per CTA

#define S_RZ (-1.4426950408889634f)  // -log2(e): r,z gates
#define S_N (2.8853900817779268f)    // 2*log2(e): n gate

// ---------------- device globals (no allocation allowed) ----------------
__device__ int g_tok64;
__device__ int g_pos64;
__device__ int g_hist[256];
__device__ int g_order[MAXB];
__device__ float g_proj[(size_t)MAXV * GDIM];  // (emb @ W_ih^T) * gate-scale

// ---------------- helpers ----------------
__device__ __forceinline__ ull ffma2(ull a, ull b, ull c) {
  ull d;
  asm("fma.rn.f32x2 %0, %1, %2, %3;" : "=l"(d) : "l"(a), "l"(b), "l"(c));
  return d;
}
__device__ __forceinline__ float pair_sum(ull a) {
  unsigned lo, hi;
  asm("mov.b64 {%0, %1}, %2;" : "=r"(lo), "=r"(hi) : "l"(a));
  return __uint_as_float(lo) + __uint_as_float(hi);
}
__device__ __forceinline__ ull mul2s(ull a, float s) {
  unsigned lo, hi;
  asm("mov.b64 {%0, %1}, %2;" : "=r"(lo), "=r"(hi) : "l"(a));
  float x = __uint_as_float(lo) * s, y = __uint_as_float(hi) * s;
  ull d;
  asm("mov.b64 %0, {%1, %2};"
      : "=l"(d)
      : "r"(__float_as_uint(x)), "r"(__float_as_uint(y)));
  return d;
}
__device__ __forceinline__ float rcp_fast(float x) {
  float y;
  asm("rcp.approx.f32 %0, %1;" : "=f"(y) : "f"(x));
  return y;
}
__device__ __forceinline__ float ex2(float x) {
  float y;
  asm("ex2.approx.f32 %0, %1;" : "=f"(y) : "f"(x));
  return y;
}
__device__ __forceinline__ int load_len_(const void* sp, int b, int T, int p64) {
  int v = p64 ? (int)((const ll*)sp)[b] : ((const int*)sp)[b];
  return min(max(v, 1), T);
}
__device__ __forceinline__ int load_tok_(const void* st, ll idx, int t64) {
  return t64 ? (int)((const ll*)st)[idx] : ((const int*)st)[idx];
}

// ---------------- preamble 1: dtype detect + length histogram (1 CTA) -------
__global__ void k_prep(const int* tok, const int* pos, int B, int T) {
  __shared__ int h_sm[256];
  int i = threadIdx.x;
  if (i == 0) {
    int t64 = 1, p64 = 1;
#pragma unroll
    for (int k = 1; k < 32; k += 2) {
      if (tok[k] != 0) t64 = 0;
      if (pos[k] != 0) p64 = 0;
    }
    g_tok64 = t64;
    g_pos64 = p64;
  }
  h_sm[i] = 0;
  __syncthreads();
  int p64 = g_pos64;
  for (int b = i; b < B; b += 256) {
    int len = load_len_(pos, b, T, p64);
    atomicAdd(&h_sm[min(T - len, 255)], 1);  // bin 0 = longest
  }
  __syncthreads();
  g_hist[i] = h_sm[i];
}

// ---------------- preamble 2: scan + scatter (1 CTA) ----------------
__global__ void k_scanscatter(const void* pos, int B, int T) {
  __shared__ int v[256];
  __shared__ int cur[256];
  int i = threadIdx.x;
  int x = g_hist[i];
  v[i] = x;
  __syncthreads();
#pragma unroll
  for (int off = 1; off < 256; off <<= 1) {
    int t = (i >= off) ? v[i - off] : 0;
    __syncthreads();
    v[i] += t;
    __syncthreads();
  }
  cur[i] = v[i] - x;
  __syncthreads();
  int p64 = g_pos64;
  for (int b = i; b < B; b += 256) {
    int len = load_len_(pos, b, T, p64);
    int bin = min(T - len, 255);
    int p = atomicAdd(&cur[bin], 1);
    if (p < MAXB) g_order[p] = b;
  }
}

// ---------------- vocab projection: g_proj = (emb @ W_ih^T) * scale --------
// k-split recipe (R13 proven), RPI 8. Grid sized to EXACTLY ONE WAVE
// (444 = 148 SM x 3 CTAs) with equal per-CTA chunks -> zero wave-
// quantization. cp.async triple buffer at prefetch distance 2.
#define PROJ_RPI 8
__global__ void __launch_bounds__(NTHR, 3) k_proj(const float* __restrict__ emb,
                                                  const float* __restrict__ W_ih,
                                                  int V) {
  __shared__ __align__(16) float e_sm[3][PROJ_RPI][2][36];  // [slot][row][kh][32+pad]
  const int tid = threadIdx.x;
  const int kh = (tid >> 4) & 1;
  const int j = (tid & 15) | ((tid >> 5) << 4);
  const int rbase = kh * 4;  // own output rows within staged block

  // W_ih half-rows for unit j, 3 gates, PRESCALED: 96 floats -> 48 ull regs
  ull wr[16], wz[16], wn[16];
  {
    const ulonglong2* p0 = (const ulonglong2*)(W_ih + j * HDIM + kh * 32);
    const ulonglong2* p1 = (const ulonglong2*)(W_ih + (HDIM + j) * HDIM + kh * 32);
    const ulonglong2* p2 = (const ulonglong2*)(W_ih + (2 * HDIM + j) * HDIM + kh * 32);
#pragma unroll
    for (int k = 0; k < 8; k++) {
      ulonglong2 a = p0[k];
      wr[2 * k] = mul2s(a.x, S_RZ);
      wr[2 * k + 1] = mul2s(a.y, S_RZ);
      ulonglong2 b = p1[k];
      wz[2 * k] = mul2s(b.x, S_RZ);
      wz[2 * k + 1] = mul2s(b.y, S_RZ);
      ulonglong2 c = p2[k];
      wn[2 * k] = mul2s(c.x, S_N);
      wn[2 * k + 1] = mul2s(c.y, S_N);
    }
  }

  int per = (V + gridDim.x - 1) / gridDim.x;
  per = (per + PROJ_RPI - 1) & ~(PROJ_RPI - 1);
  const int vbeg = blockIdx.x * per;
  const int vend = min(vbeg + per, V);
  if (vbeg >= vend) return;
  const int niter = (vend - vbeg + PROJ_RPI - 1) / PROJ_RPI;

  const unsigned smem_base = (unsigned)__cvta_generic_to_shared(e_sm);

  // loaders: all 128 threads, one 16B cp.async (8 rows x 16 float4).
  // float4 chunk c of a row maps to [kh' = c>>3][(c&7)*4] in padded layout.
  const int lrow = tid >> 4, lchunk = tid & 15;
  const unsigned lpad_off =
      (unsigned)(((lchunk >> 3) * 36 + (lchunk & 7) * 4) * 4);  // bytes in row

  auto issue_block = [&](int it, int s) {
    int v = vbeg + it * PROJ_RPI + lrow;
    if (v >= vend) v = vend - 1;  // clamp: data unused, address valid
    unsigned dst =
        smem_base + (unsigned)((s * PROJ_RPI + lrow) * 72 * 4) + lpad_off;
    const float* src = emb + (ll)v * HDIM + lchunk * 4;
    asm volatile("cp.async.cg.shared.global [%0], [%1], 16;" ::"r"(dst),
                 "l"(src));
    asm volatile("cp.async.commit_group;" ::: "memory");
  };

  issue_block(0, 0);
  if (niter > 1) issue_block(1, 1);

  for (int it = 0; it < niter; it++) {
    const int slot = it % 3;
    if (it + 1 < niter)
      asm volatile("cp.async.wait_group 1;" ::: "memory");
    else
      asm volatile("cp.async.wait_group 0;" ::: "memory");
    __syncthreads();

    if (it + 2 < niter)
      issue_block(it + 2, (it + 2) % 3);
    else
      asm volatile("cp.async.commit_group;" ::: "memory");

    ull acc[PROJ_RPI][3];
#pragma unroll
    for (int r = 0; r < PROJ_RPI; r++) {
      acc[r][0] = 0ull;
      acc[r][1] = 0ull;
      acc[r][2] = 0ull;
    }
#pragma unroll
    for (int k = 0; k < 8; k++) {
#pragma unroll
      for (int r = 0; r < PROJ_RPI; r++) {
        ulonglong2 q = ((const ulonglong2*)e_sm[slot][r][kh])[k];
        acc[r][0] = ffma2(wr[2 * k], q.x, acc[r][0]);
        acc[r][0] = ffma2(wr[2 * k + 1], q.y, acc[r][0]);
        acc[r][1] = ffma2(wz[2 * k], q.x, acc[r][1]);
        acc[r][1] = ffma2(wz[2 * k + 1], q.y, acc[r][1]);
        acc[r][2] = ffma2(wn[2 * k], q.x, acc[r][2]);
        acc[r][2] = ffma2(wn[2 * k + 1], q.y, acc[r][2]);
      }
    }

    float f[PROJ_RPI][3];
#pragma unroll
    for (int r = 0; r < PROJ_RPI; r++) {
#pragma unroll
      for (int gg = 0; gg < 3; gg++) {
        float p = pair_sum(acc[r][gg]);
        f[r][gg] = p + __shfl_xor_sync(0xffffffffu, p, 16);
      }
    }

    const int v0 = vbeg + it * PROJ_RPI + rbase;
#pragma unroll
    for (int r = 0; r < 4; r++) {
      int v = v0 + r;
      if (v < vend) {
        float* dst = g_proj + (ll)v * GDIM + j;
        dst[0] = f[rbase + r][0];
        dst[64] = f[rbase + r][1];
        dst[128] = f[rbase + r][2];
      }
    }
    __syncthreads();
  }
  asm volatile("cp.async.wait_group 0;" ::: "memory");
}

// ---------------- fused GRU recurrence (proven R13/R14 config) -------------
// CTA = 128 threads. kh = (tid>>4)&1, j = (tid&15)|((tid>>5)<<4).
// Thread: partial dots (its 32 k's) for 4 rows x 3 gates with PRESCALED W
// in REGISTERS (96 floats), shfl.xor(16) combines halves, ex2/rcp gates +
// h-update for own 2 rows (h carried in registers). gi prefetched one full
// step ahead. One barrier per step; 2x unrolled.
__global__ void __launch_bounds__(NTHR, 3) k_gru(
    const void* __restrict__ seq_token, const void* __restrict__ seq_pos,
    const float* __restrict__ W_hh, float* __restrict__ out, int B, int T) {
  __shared__ int tok_sm[ROWS][MAXT];  // byte offsets: tok * GDIM * 4
  __shared__ __align__(16) float h_sm[2][ROWS][2][36];  // [buf][row][kh][32+pad]
  __shared__ int s_row[ROWS], s_len[ROWS];

  const int tid = threadIdx.x;
  const int kh = (tid >> 4) & 1;
  const int j = (tid & 15) | ((tid >> 5) << 4);
  const int rA = kh * 2, rB = rA + 1;  // own rows
  const int tok64 = g_tok64;
  const int jh = j >> 5, jl = j & 31;

  if (tid < ROWS) {
    int idx = ROWS * blockIdx.x + tid;
    int row = (idx < B) ? g_order[idx] : -1;
    s_row[tid] = row;
    s_len[tid] = (row >= 0) ? load_len_(seq_pos, row, T, g_pos64) : 0;
  }
  __syncthreads();
  int tmax = max(max(s_len[0], s_len[1]), max(s_len[2], s_len[3]));
  int tsteps = (tmax + 1) & ~1;
  if (tsteps > MAXT - 1) tsteps = MAXT - 1;
  if (tsteps < tmax) tsteps = tmax;
  const int lenA = s_len[rA], lenB = s_len[rB];

  // stage token BYTE offsets into smem (+ zero sentinel for prefetch tail)
#pragma unroll
  for (int r = 0; r < ROWS; r++) {
    int rw = s_row[r];
    for (int i = tid; i < tsteps; i += NTHR) {
      int tk = (rw >= 0 && i < T) ? load_tok_(seq_token, (ll)rw * T + i, tok64) : 0;
      tok_sm[r][i] = tk * (GDIM * 4);
    }
  }
  if (tid < ROWS) tok_sm[tid][tsteps] = 0;  // sentinel

  // W_hh half-rows for unit j, 3 gates, PRESCALED: 96 floats -> 48 ull regs
  ull wr[16], wz[16], wn[16];
  {
    const ulonglong2* p0 = (const ulonglong2*)(W_hh + j * HDIM + kh * 32);
    const ulonglong2* p1 = (const ulonglong2*)(W_hh + (HDIM + j) * HDIM + kh * 32);
    const ulonglong2* p2 = (const ulonglong2*)(W_hh + (2 * HDIM + j) * HDIM + kh * 32);
#pragma unroll
    for (int k = 0; k < 8; k++) {
      ulonglong2 a = p0[k];
      wr[2 * k] = mul2s(a.x, S_RZ);
      wr[2 * k + 1] = mul2s(a.y, S_RZ);
      ulonglong2 b = p1[k];
      wz[2 * k] = mul2s(b.x, S_RZ);
      wz[2 * k + 1] = mul2s(b.y, S_RZ);
      ulonglong2 c = p2[k];
      wn[2 * k] = mul2s(c.x, S_N);
      wn[2 * k + 1] = mul2s(c.y, S_N);
    }
  }

  // init h = 0 in buffer 0 (own-row slots); own h also lives in registers
  float hoA = 0.0f, hoB = 0.0f;
  h_sm[0][rA][jh][jl] = 0.0f;
  h_sm[0][rB][jh][jl] = 0.0f;
  __syncthreads();  // tok_sm + h ready

  const char* gbaseJ = (const char*)g_proj + (unsigned)(j * 4);

  // gi for t=0 (own 2 rows x 3 gates)
  float grA, gzA, gnA, grB, gzB, gnB;
  {
    const float* pA = (const float*)(gbaseJ + (unsigned)tok_sm[rA][0]);
    const float* pB = (const float*)(gbaseJ + (unsigned)tok_sm[rB][0]);
    grA = pA[0]; gzA = pA[64]; gnA = pA[128];
    grB = pB[0]; gzB = pB[64]; gnB = pB[128];
  }

// one GRU step: prefetches gi for tt+1, consumes gi of tt, updates h.
#define GRU_STEP(CUR, NXT, tt)                                                 \
  do {                                                                         \
    const float* pA = (const float*)(gbaseJ + (unsigned)tok_sm[rA][(tt) + 1]); \
    const float* pB = (const float*)(gbaseJ + (unsigned)tok_sm[rB][(tt) + 1]); \
    float qrA = pA[0], qzA = pA[64], qnA = pA[128];                            \
    float qrB = pB[0], qzB = pB[64], qnB = pB[128];                            \
    ull acc[ROWS][3];                                                          \
    _Pragma("unroll") for (int r = 0; r < ROWS; r++) {                         \
      acc[r][0] = 0ull;                                                        \
      acc[r][1] = 0ull;                                                        \
      acc[r][2] = 0ull;                                                        \
    }                                                                          \
    _Pragma("unroll") for (int k = 0; k < 8; k++) {                            \
      _Pragma("unroll") for (int r = 0; r < ROWS; r++) {                       \
        ulonglong2 hq = ((const ulonglong2*)h_sm[CUR][r][kh])[k];              \
        acc[r][0] = ffma2(wr[2 * k], hq.x, acc[r][0]);                         \
        acc[r][0] = ffma2(wr[2 * k + 1], hq.y, acc[r][0]);                     \
        acc[r][1] = ffma2(wz[2 * k], hq.x, acc[r][1]);                         \
        acc[r][1] = ffma2(wz[2 * k + 1], hq.y, acc[r][1]);                     \
        acc[r][2] = ffma2(wn[2 * k], hq.x, acc[r][2]);                         \
        acc[r][2] = ffma2(wn[2 * k + 1], hq.y, acc[r][2]);                     \
      }                                                                        \
    }                                                                          \
    float f[ROWS][3];                                                          \
    _Pragma("unroll") for (int r = 0; r < ROWS; r++) {                         \
      _Pragma("unroll") for (int gg = 0; gg < 3; gg++) {                       \
        float p = pair_sum(acc[r][gg]);                                        \
        f[r][gg] = p + __shfl_xor_sync(0xffffffffu, p, 16);                    \
      }                                                                        \
    }                                                                          \
    {                                                                          \
      float rrA = rcp_fast(1.0f + ex2(grA + f[rA][0]));                        \
      float zzA = rcp_fast(1.0f + ex2(gzA + f[rA][1]));                        \
      float nnA = 1.0f - 2.0f * rcp_fast(ex2(gnA + rrA * f[rA][2]) + 1.0f);    \
      float hnA = (1.0f - zzA) * nnA + zzA * hoA;                              \
      hoA = ((tt) < lenA) ? hnA : hoA;                                         \
      h_sm[NXT][rA][jh][jl] = hoA;                                             \
      float rrB = rcp_fast(1.0f + ex2(grB + f[rB][0]));                        \
      float zzB = rcp_fast(1.0f + ex2(gzB + f[rB][1]));                        \
      float nnB = 1.0f - 2.0f * rcp_fast(ex2(gnB + rrB * f[rB][2]) + 1.0f);    \
      float hnB = (1.0f - zzB) * nnB + zzB * hoB;                              \
      hoB = ((tt) < lenB) ? hnB : hoB;                                         \
      h_sm[NXT][rB][jh][jl] = hoB;                                             \
    }                                                                          \
    grA = qrA; gzA = qzA; gnA = qnA;                                           \
    grB = qrB; gzB = qzB; gnB = qnB;                                           \
    __syncthreads();                                                           \
  } while (0)

  int t = 0;
  for (; t + 1 < tsteps; t += 2) {
    GRU_STEP(0, 1, t);
    GRU_STEP(1, 0, t + 1);
  }
  if (t < tsteps) {  // odd tail
    GRU_STEP(0, 1, t);
  }
#undef GRU_STEP

  {
    int row = s_row[rA];
    if (row >= 0) out[(ll)row * HDIM + j] = hoA;
    row = s_row[rB];
    if (row >= 0) out[(ll)row * HDIM + j] = hoB;
  }
}

// ---------------- launch ----------------
extern "C" void kernel_launch(void* const* d_in, const int* in_sizes, int n_in,
                              void* d_out, int out_size) {
  const void* tok = d_in[0];
  const void* pos = d_in[1];
  const float* emb = (const float*)d_in[2];
  const float* wih = (const float*)d_in[3];
  const float* whh = (const float*)d_in[4];
  float* out = (float*)d_out;

  const int B = in_sizes[1];
  const int T = in_sizes[0] / (B > 0 ? B : 1);
  int V = in_sizes[2] / HDIM;
  if (V > MAXV) V = MAXV;

  k_prep<<<1, 256>>>((const int*)tok, (const int*)pos, B, T);
  k_scanscatter<<<1, 256>>>(pos, B, T);
  // single perfectly-balanced wave: 148 SMs x 3 CTAs
  k_proj<<<444, NTHR>>>(emb, wih, V);

  const int nblk = (B + ROWS - 1) / ROWS;
  k_gru<<<nblk, NTHR>>>(tok, pos, whh, out, B, T);
}

// round 17
// speedup vs baseline: 1.2976x; 1.1200x over previous
#include <cuda_runtime.h>

typedef unsigned long long ull;
typedef long long ll;

#define HDIM 64
#define GDIM 192  // 3*HDIM
#define MAXT 256
#define MAXB 16384
#define MAXV 102400
#define NTHR 128  // (k-half) x (64 units)
#define ROWS 4    // rows per CTA

#define S_RZ (-1.4426950408889634f)  // -log2(e): r,z gates
#define S_N (2.8853900817779268f)    // 2*log2(e): n gate

// ---------------- device globals (no allocation allowed) ----------------
__device__ int g_tok64;
__device__ int g_pos64;
__device__ int g_order[MAXB];
__device__ float g_proj[(size_t)MAXV * GDIM];  // (emb @ W_ih^T) * gate-scale

// ---------------- helpers ----------------
__device__ __forceinline__ ull ffma2(ull a, ull b, ull c) {
  ull d;
  asm("fma.rn.f32x2 %0, %1, %2, %3;" : "=l"(d) : "l"(a), "l"(b), "l"(c));
  return d;
}
__device__ __forceinline__ float pair_sum(ull a) {
  unsigned lo, hi;
  asm("mov.b64 {%0, %1}, %2;" : "=r"(lo), "=r"(hi) : "l"(a));
  return __uint_as_float(lo) + __uint_as_float(hi);
}
__device__ __forceinline__ ull mul2s(ull a, float s) {
  unsigned lo, hi;
  asm("mov.b64 {%0, %1}, %2;" : "=r"(lo), "=r"(hi) : "l"(a));
  float x = __uint_as_float(lo) * s, y = __uint_as_float(hi) * s;
  ull d;
  asm("mov.b64 %0, {%1, %2};"
      : "=l"(d)
      : "r"(__float_as_uint(x)), "r"(__float_as_uint(y)));
  return d;
}
__device__ __forceinline__ float rcp_fast(float x) {
  float y;
  asm("rcp.approx.f32 %0, %1;" : "=f"(y) : "f"(x));
  return y;
}
__device__ __forceinline__ float ex2(float x) {
  float y;
  asm("ex2.approx.f32 %0, %1;" : "=f"(y) : "f"(x));
  return y;
}
__device__ __forceinline__ int load_len_(const void* sp, int b, int T, int p64) {
  int v = p64 ? (int)((const ll*)sp)[b] : ((const int*)sp)[b];
  return min(max(v, 1), T);
}
__device__ __forceinline__ int load_tok_(const void* st, ll idx, int t64) {
  return t64 ? (int)((const ll*)st)[idx] : ((const int*)st)[idx];
}

// ---------------- fused proj + preamble ----------------
// Grid = 444 CTAs = exactly one wave (148 SM x 3). Block 0 runs the preamble
// (detect + hist + 256-bin scan with 128 threads + scatter) CONCURRENTLY
// with blocks 1..443 doing the vocab projection. k_gru consumes g_order /
// g_proj only after this kernel retires.
#define PROJ_RPI 8
__global__ void __launch_bounds__(NTHR, 3) k_projprep(
    const float* __restrict__ emb, const float* __restrict__ W_ih,
    const int* __restrict__ tok, const void* __restrict__ pos, int V, int B,
    int T) {
  __shared__ __align__(16) float e_sm[3][PROJ_RPI][2][36];  // [slot][row][kh][32+pad]
  __shared__ int hist[256];
  __shared__ int scan_v[256];
  __shared__ int cursor[256];
  __shared__ int flags[1];
  const int tid = threadIdx.x;

  if (blockIdx.x == 0) {
    // ---------- preamble path (1 CTA, 128 threads) ----------
    if (tid == 0) {
      int t64 = 1, p64 = 1;
#pragma unroll
      for (int k = 1; k < 32; k += 2) {
        if (tok[k] != 0) t64 = 0;
        if (((const int*)pos)[k] != 0) p64 = 0;
      }
      g_tok64 = t64;
      g_pos64 = p64;
      flags[0] = p64;
    }
    hist[tid] = 0;
    hist[tid + 128] = 0;
    __syncthreads();
    const int p64 = flags[0];

    for (int b = tid; b < B; b += NTHR) {
      int len = load_len_(pos, b, T, p64);
      atomicAdd(&hist[min(T - len, 255)], 1);  // bin 0 = longest
    }
    __syncthreads();

    // 256-bin inclusive scan with 128 threads: two independent half-scans
    int x0 = hist[tid], x1 = hist[tid + 128];
    scan_v[tid] = x0;
    scan_v[tid + 128] = x1;
    __syncthreads();
#pragma unroll
    for (int off = 1; off < 128; off <<= 1) {
      int t0 = (tid >= off) ? scan_v[tid - off] : 0;
      int t1 = (tid >= off) ? scan_v[128 + tid - off] : 0;
      __syncthreads();
      scan_v[tid] += t0;
      scan_v[128 + tid] += t1;
      __syncthreads();
    }
    const int lowtot = scan_v[127];
    cursor[tid] = scan_v[tid] - x0;                     // exclusive, lower half
    cursor[128 + tid] = scan_v[128 + tid] + lowtot - x1;  // upper half + offset
    __syncthreads();

    for (int b = tid; b < B; b += NTHR) {
      int len = load_len_(pos, b, T, p64);
      int bin = min(T - len, 255);
      int p = atomicAdd(&cursor[bin], 1);
      if (p < MAXB) g_order[p] = b;
    }
    return;
  }

  // ---------- projection path (blocks 1..gridDim-1) ----------
  const int kh = (tid >> 4) & 1;
  const int j = (tid & 15) | ((tid >> 5) << 4);
  const int rbase = kh * 4;  // own output rows within staged block

  // W_ih half-rows for unit j, 3 gates, PRESCALED: 96 floats -> 48 ull regs
  ull wr[16], wz[16], wn[16];
  {
    const ulonglong2* p0 = (const ulonglong2*)(W_ih + j * HDIM + kh * 32);
    const ulonglong2* p1 = (const ulonglong2*)(W_ih + (HDIM + j) * HDIM + kh * 32);
    const ulonglong2* p2 = (const ulonglong2*)(W_ih + (2 * HDIM + j) * HDIM + kh * 32);
#pragma unroll
    for (int k = 0; k < 8; k++) {
      ulonglong2 a = p0[k];
      wr[2 * k] = mul2s(a.x, S_RZ);
      wr[2 * k + 1] = mul2s(a.y, S_RZ);
      ulonglong2 b = p1[k];
      wz[2 * k] = mul2s(b.x, S_RZ);
      wz[2 * k + 1] = mul2s(b.y, S_RZ);
      ulonglong2 c = p2[k];
      wn[2 * k] = mul2s(c.x, S_N);
      wn[2 * k + 1] = mul2s(c.y, S_N);
    }
  }

  const int nb = (int)gridDim.x - 1;  // 443 proj blocks
  int per = (V + nb - 1) / nb;
  per = (per + PROJ_RPI - 1) & ~(PROJ_RPI - 1);
  const int vbeg = ((int)blockIdx.x - 1) * per;
  const int vend = min(vbeg + per, V);
  if (vbeg >= vend) return;
  const int niter = (vend - vbeg + PROJ_RPI - 1) / PROJ_RPI;

  const unsigned smem_base = (unsigned)__cvta_generic_to_shared(e_sm);

  // loaders: all 128 threads, one 16B cp.async (8 rows x 16 float4).
  const int lrow = tid >> 4, lchunk = tid & 15;
  const unsigned lpad_off =
      (unsigned)(((lchunk >> 3) * 36 + (lchunk & 7) * 4) * 4);  // bytes in row

  auto issue_block = [&](int it, int s) {
    int v = vbeg + it * PROJ_RPI + lrow;
    if (v >= vend) v = vend - 1;  // clamp: data unused, address valid
    unsigned dst =
        smem_base + (unsigned)((s * PROJ_RPI + lrow) * 72 * 4) + lpad_off;
    const float* src = emb + (ll)v * HDIM + lchunk * 4;
    asm volatile("cp.async.cg.shared.global [%0], [%1], 16;" ::"r"(dst),
                 "l"(src));
    asm volatile("cp.async.commit_group;" ::: "memory");
  };

  issue_block(0, 0);
  if (niter > 1) issue_block(1, 1);

  for (int it = 0; it < niter; it++) {
    const int slot = it % 3;
    if (it + 1 < niter)
      asm volatile("cp.async.wait_group 1;" ::: "memory");
    else
      asm volatile("cp.async.wait_group 0;" ::: "memory");
    // single barrier per iteration: orders (a) staged slot `it` visible to
    // all, and (b) every thread's reads of slot it-1 complete BEFORE the
    // cp.async below overwrites that slot.
    __syncthreads();

    if (it + 2 < niter)
      issue_block(it + 2, (it + 2) % 3);
    else
      asm volatile("cp.async.commit_group;" ::: "memory");

    ull acc[PROJ_RPI][3];
#pragma unroll
    for (int r = 0; r < PROJ_RPI; r++) {
      acc[r][0] = 0ull;
      acc[r][1] = 0ull;
      acc[r][2] = 0ull;
    }
#pragma unroll
    for (int k = 0; k < 8; k++) {
#pragma unroll
      for (int r = 0; r < PROJ_RPI; r++) {
        ulonglong2 q = ((const ulonglong2*)e_sm[slot][r][kh])[k];
        acc[r][0] = ffma2(wr[2 * k], q.x, acc[r][0]);
        acc[r][0] = ffma2(wr[2 * k + 1], q.y, acc[r][0]);
        acc[r][1] = ffma2(wz[2 * k], q.x, acc[r][1]);
        acc[r][1] = ffma2(wz[2 * k + 1], q.y, acc[r][1]);
        acc[r][2] = ffma2(wn[2 * k], q.x, acc[r][2]);
        acc[r][2] = ffma2(wn[2 * k + 1], q.y, acc[r][2]);
      }
    }

    // butterfly combine: each lane sends the partial its partner needs
    // (select by kh), receives partner's partial of its OWN row. 12 shfls.
    float f[4][3];
#pragma unroll
    for (int i = 0; i < 4; i++) {
#pragma unroll
      for (int gg = 0; gg < 3; gg++) {
        float plo = pair_sum(acc[i][gg]);       // rows 0..3
        float phi = pair_sum(acc[4 + i][gg]);   // rows 4..7
        float own = kh ? phi : plo;
        float oth = kh ? plo : phi;
        f[i][gg] = own + __shfl_xor_sync(0xffffffffu, oth, 16);
      }
    }

    const int v0 = vbeg + it * PROJ_RPI + rbase;
#pragma unroll
    for (int r = 0; r < 4; r++) {
      int v = v0 + r;
      if (v < vend) {
        float* dst = g_proj + (ll)v * GDIM + j;
        dst[0] = f[r][0];
        dst[64] = f[r][1];
        dst[128] = f[r][2];
      }
    }
  }
  asm volatile("cp.async.wait_group 0;" ::: "memory");
}

// ---------------- fused GRU recurrence (proven config + butterfly shfl) ----
// CTA = 128 threads. kh = (tid>>4)&1, j = (tid&15)|((tid>>5)<<4).
// Thread: partial dots (its 32 k's) for 4 rows x 3 gates with PRESCALED W
// in REGISTERS (96 floats), butterfly shfl.xor(16) combine (6 shfls),
// ex2/rcp gates + h-update for own 2 rows (h carried in registers). gi
// prefetched one full step ahead. One barrier per step; 2x unrolled.
__global__ void __launch_bounds__(NTHR, 3) k_gru(
    const void* __restrict__ seq_token, const void* __restrict__ seq_pos,
    const float* __restrict__ W_hh, float* __restrict__ out, int B, int T) {
  __shared__ int tok_sm[ROWS][MAXT];  // byte offsets: tok * GDIM * 4
  __shared__ __align__(16) float h_sm[2][ROWS][2][36];  // [buf][row][kh][32+pad]
  __shared__ int s_row[ROWS], s_len[ROWS];

  const int tid = threadIdx.x;
  const int kh = (tid >> 4) & 1;
  const int j = (tid & 15) | ((tid >> 5) << 4);
  const int rA = kh * 2, rB = rA + 1;  // own rows
  const int tok64 = g_tok64;
  const int jh = j >> 5, jl = j & 31;

  if (tid < ROWS) {
    int idx = ROWS * blockIdx.x + tid;
    int row = (idx < B) ? g_order[idx] : -1;
    s_row[tid] = row;
    s_len[tid] = (row >= 0) ? load_len_(seq_pos, row, T, g_pos64) : 0;
  }
  __syncthreads();
  int tmax = max(max(s_len[0], s_len[1]), max(s_len[2], s_len[3]));
  int tsteps = (tmax + 1) & ~1;
  if (tsteps > MAXT - 1) tsteps = MAXT - 1;
  if (tsteps < tmax) tsteps = tmax;
  const int lenA = s_len[rA], lenB = s_len[rB];

  // stage token BYTE offsets into smem (+ zero sentinel for prefetch tail)
#pragma unroll
  for (int r = 0; r < ROWS; r++) {
    int rw = s_row[r];
    for (int i = tid; i < tsteps; i += NTHR) {
      int tk = (rw >= 0 && i < T) ? load_tok_(seq_token, (ll)rw * T + i, tok64) : 0;
      tok_sm[r][i] = tk * (GDIM * 4);
    }
  }
  if (tid < ROWS) tok_sm[tid][tsteps] = 0;  // sentinel

  // W_hh half-rows for unit j, 3 gates, PRESCALED: 96 floats -> 48 ull regs
  ull wr[16], wz[16], wn[16];
  {
    const ulonglong2* p0 = (const ulonglong2*)(W_hh + j * HDIM + kh * 32);
    const ulonglong2* p1 = (const ulonglong2*)(W_hh + (HDIM + j) * HDIM + kh * 32);
    const ulonglong2* p2 = (const ulonglong2*)(W_hh + (2 * HDIM + j) * HDIM + kh * 32);
#pragma unroll
    for (int k = 0; k < 8; k++) {
      ulonglong2 a = p0[k];
      wr[2 * k] = mul2s(a.x, S_RZ);
      wr[2 * k + 1] = mul2s(a.y, S_RZ);
      ulonglong2 b = p1[k];
      wz[2 * k] = mul2s(b.x, S_RZ);
      wz[2 * k + 1] = mul2s(b.y, S_RZ);
      ulonglong2 c = p2[k];
      wn[2 * k] = mul2s(c.x, S_N);
      wn[2 * k + 1] = mul2s(c.y, S_N);
    }
  }

  // init h = 0 in buffer 0 (own-row slots); own h also lives in registers
  float hoA = 0.0f, hoB = 0.0f;
  h_sm[0][rA][jh][jl] = 0.0f;
  h_sm[0][rB][jh][jl] = 0.0f;
  __syncthreads();  // tok_sm + h ready

  const char* gbaseJ = (const char*)g_proj + (unsigned)(j * 4);

  // gi for t=0 (own 2 rows x 3 gates)
  float grA, gzA, gnA, grB, gzB, gnB;
  {
    const float* pA = (const float*)(gbaseJ + (unsigned)tok_sm[rA][0]);
    const float* pB = (const float*)(gbaseJ + (unsigned)tok_sm[rB][0]);
    grA = pA[0]; gzA = pA[64]; gnA = pA[128];
    grB = pB[0]; gzB = pB[64]; gnB = pB[128];
  }

// one GRU step: prefetches gi for tt+1, consumes gi of tt, updates h.
// Butterfly combine: lane sends partial of PARTNER's row, receives partner's
// partial of its OWN row (6 shfls instead of 12; FSEL selects by kh).
#define GRU_STEP(CUR, NXT, tt)                                                 \
  do {                                                                         \
    const float* pA = (const float*)(gbaseJ + (unsigned)tok_sm[rA][(tt) + 1]); \
    const float* pB = (const float*)(gbaseJ + (unsigned)tok_sm[rB][(tt) + 1]); \
    float qrA = pA[0], qzA = pA[64], qnA = pA[128];                            \
    float qrB = pB[0], qzB = pB[64], qnB = pB[128];                            \
    ull acc[ROWS][3];                                                          \
    _Pragma("unroll") for (int r = 0; r < ROWS; r++) {                         \
      acc[r][0] = 0ull;                                                        \
      acc[r][1] = 0ull;                                                        \
      acc[r][2] = 0ull;                                                        \
    }                                                                          \
    _Pragma("unroll") for (int k = 0; k < 8; k++) {                            \
      _Pragma("unroll") for (int r = 0; r < ROWS; r++) {                       \
        ulonglong2 hq = ((const ulonglong2*)h_sm[CUR][r][kh])[k];              \
        acc[r][0] = ffma2(wr[2 * k], hq.x, acc[r][0]);                         \
        acc[r][0] = ffma2(wr[2 * k + 1], hq.y, acc[r][0]);                     \
        acc[r][1] = ffma2(wz[2 * k], hq.x, acc[r][1]);                         \
        acc[r][1] = ffma2(wz[2 * k + 1], hq.y, acc[r][1]);                     \
        acc[r][2] = ffma2(wn[2 * k], hq.x, acc[r][2]);                         \
        acc[r][2] = ffma2(wn[2 * k + 1], hq.y, acc[r][2]);                     \
      }                                                                        \
    }                                                                          \
    float fA[3], fB[3];                                                        \
    _Pragma("unroll") for (int gg = 0; gg < 3; gg++) {                         \
      float p0 = pair_sum(acc[0][gg]);                                         \
      float p1 = pair_sum(acc[1][gg]);                                         \
      float p2 = pair_sum(acc[2][gg]);                                         \
      float p3 = pair_sum(acc[3][gg]);                                         \
      float ownA = kh ? p2 : p0;                                               \
      float othA = kh ? p0 : p2;                                               \
      float ownB = kh ? p3 : p1;                                               \
      float othB = kh ? p1 : p3;                                               \
      fA[gg] = ownA + __shfl_xor_sync(0xffffffffu, othA, 16);                  \
      fB[gg] = ownB + __shfl_xor_sync(0xffffffffu, othB, 16);                  \
    }                                                                          \
    {                                                                          \
      float rrA = rcp_fast(1.0f + ex2(grA + fA[0]));                           \
      float zzA = rcp_fast(1.0f + ex2(gzA + fA[1]));                           \
      float nnA = 1.0f - 2.0f * rcp_fast(ex2(gnA + rrA * fA[2]) + 1.0f);       \
      float hnA = (1.0f - zzA) * nnA + zzA * hoA;                              \
      hoA = ((tt) < lenA) ? hnA : hoA;                                         \
      h_sm[NXT][rA][jh][jl] = hoA;                                             \
      float rrB = rcp_fast(1.0f + ex2(grB + fB[0]));                           \
      float zzB = rcp_fast(1.0f + ex2(gzB + fB[1]));                           \
      float nnB = 1.0f - 2.0f * rcp_fast(ex2(gnB + rrB * fB[2]) + 1.0f);       \
      float hnB = (1.0f - zzB) * nnB + zzB * hoB;                              \
      hoB = ((tt) < lenB) ? hnB : hoB;                                         \
      h_sm[NXT][rB][jh][jl] = hoB;                                             \
    }                                                                          \
    grA = qrA; gzA = qzA; gnA = qnA;                                           \
    grB = qrB; gzB = qzB; gnB = qnB;                                           \
    __syncthreads();                                                           \
  } while (0)

  int t = 0;
  for (; t + 1 < tsteps; t += 2) {
    GRU_STEP(0, 1, t);
    GRU_STEP(1, 0, t + 1);
  }
  if (t < tsteps) {  // odd tail
    GRU_STEP(0, 1, t);
  }
#undef GRU_STEP

  {
    int row = s_row[rA];
    if (row >= 0) out[(ll)row * HDIM + j] = hoA;
    row = s_row[rB];
    if (row >= 0) out[(ll)row * HDIM + j] = hoB;
  }
}

// ---------------- launch ----------------
extern "C" void kernel_launch(void* const* d_in, const int* in_sizes, int n_in,
                              void* d_out, int out_size) {
  const void* tok = d_in[0];
  const void* pos = d_in[1];
  const float* emb = (const float*)d_in[2];
  const float* wih = (const float*)d_in[3];
  const float* whh = (const float*)d_in[4];
  float* out = (float*)d_out;

  const int B = in_sizes[1];
  const int T = in_sizes[0] / (B > 0 ? B : 1);
  int V = in_sizes[2] / HDIM;
  if (V > MAXV) V = MAXV;

  // one wave: block 0 = preamble, blocks 1..443 = projection
  k_projprep<<<444, NTHR>>>(emb, wih, (const int*)tok, pos, V, B, T);

  const int nblk = (B + ROWS - 1) / ROWS;
  k_gru<<<nblk, NTHR>>>(tok, pos, whh, out, B, T);
}